// round 1
// baseline (speedup 1.0000x reference)
#include <cuda_runtime.h>
#include <math.h>

// ---------------------------------------------------------------------------
// JIIF pipeline, fp32 baseline with layer-0 factorization.
//
// Shapes (fixed by the problem):
//   feat      [4,128,64,64]
//   coord     [4,65536,2]
//   hr_guide  [4,128,256,256]
//   lr_guide  [4,128,64,64]
//   W0 [386,1024] b0[1024]; W1[1024,512]; W2[512,256]; W3[256,128]; W4[128,2]
//   out       [4,65536,1]  (float32, 262144 elems)
// ---------------------------------------------------------------------------

namespace {
constexpr int BATCH   = 4;
constexpr int NPTS    = 65536;            // points per batch
constexpr int PTOT    = BATCH * NPTS;     // 262144
constexpr int RTOT    = PTOT * 4;         // 1048576 rows
constexpr int CHUNK_PTS  = 65536;         // points per backend chunk
constexpr int CHUNK_ROWS = CHUNK_PTS * 4; // 262144
constexpr int NCHUNK  = 4;
}

// ------------------------------- scratch -----------------------------------
__device__ __align__(256) float g_Thr[(size_t)BATCH * 256 * 256 * 128]; // hr in HWC
__device__ __align__(256) float g_G[(size_t)PTOT * 128];                // gathered hr per point
__device__ __align__(256) float g_V[(size_t)PTOT * 1024];               // per-point proj
__device__ __align__(256) float g_CellIn[(size_t)BATCH * 4096 * 256];   // [feat,lr] per cell
__device__ __align__(256) float g_U[(size_t)BATCH * 4096 * 1024];       // per-cell proj
__device__ __align__(256) float g_Wcell[256 * 1024];                    // [W0a; -W0c]
__device__ __align__(256) float g_Whr[128 * 1024];                      // W0b + W0c
__device__ __align__(256) int   g_cellidx[RTOT];
__device__ __align__(256) float g_rel[(size_t)RTOT * 2];
__device__ __align__(256) float g_H1[(size_t)CHUNK_ROWS * 1024];
__device__ __align__(256) float g_H2[(size_t)CHUNK_ROWS * 512];
__device__ __align__(256) float g_H3[(size_t)CHUNK_ROWS * 256];
__device__ __align__(256) float g_H4[(size_t)CHUNK_ROWS * 128];

// ------------------------- helpers ------------------------------------------
// ((c + 1) * n - 1) * 0.5, forced to plain rn ops (no FMA contraction) so the
// rounding matches the reference's separate mul/sub exactly.
__device__ __forceinline__ float gridpos(float c, float n) {
    return __fmul_rn(__fsub_rn(__fmul_rn(__fadd_rn(c, 1.0f), n), 1.0f), 0.5f);
}

// ------------------------- kernels ------------------------------------------

// hr_guide [B,C,H*W] -> g_Thr [B, H*W, C]   (C=128, S=65536)
__global__ void k_transpose_hr(const float* __restrict__ in) {
    __shared__ float t[32][33];
    const size_t S = 65536, C = 128;
    int b  = blockIdx.z;
    int s0 = blockIdx.x * 32;
    int c0 = blockIdx.y * 32;
    int x  = threadIdx.x;              // 0..31
    #pragma unroll
    for (int j = threadIdx.y; j < 32; j += 8)
        t[j][x] = in[((size_t)b * C + (c0 + j)) * S + s0 + x];
    __syncthreads();
    #pragma unroll
    for (int j = threadIdx.y; j < 32; j += 8)
        g_Thr[((size_t)b * S + (s0 + j)) * C + c0 + x] = t[x][j];
}

// Build Wcell = [W0 rows 0..127 ; -(W0 rows 256..383)] and Whr = W0[128:256]+W0[256:384]
__global__ void k_build_w(const float* __restrict__ W0) {
    int idx = blockIdx.x * 256 + threadIdx.x;
    if (idx < 256 * 1024) {
        int k = idx >> 10, j = idx & 1023;
        g_Wcell[idx] = (k < 128) ? W0[k * 1024 + j] : -W0[(128 + k) * 1024 + j];
    } else {
        int t = idx - 256 * 1024;   // < 128*1024
        int k = t >> 10, j = t & 1023;
        g_Whr[t] = W0[(128 + k) * 1024 + j] + W0[(256 + k) * 1024 + j];
    }
}

// CellIn[b, cell, 0:128]=feat[b,:,cell], [128:256]=lr[b,:,cell]
__global__ void k_build_cellin(const float* __restrict__ feat,
                               const float* __restrict__ lr) {
    int idx  = blockIdx.x * 256 + threadIdx.x;      // < 4*4096*256
    int c    = idx & 255;
    int cell = (idx >> 8) & 4095;
    int b    = idx >> 20;
    float v;
    if (c < 128) v = feat[((size_t)(b * 128 + c)) * 4096 + cell];
    else         v = lr  [((size_t)(b * 128 + (c - 128))) * 4096 + cell];
    g_CellIn[idx] = v;
}

// Per (point, branch): cell index (or -1) and rel_coord.
__global__ void k_index(const float* __restrict__ coord) {
    int r = blockIdx.x * 256 + threadIdx.x;   // < RTOT
    int br = r & 3;
    int p  = r >> 2;
    int b  = p >> 16;
    float cy = coord[2 * (size_t)p], cx = coord[2 * (size_t)p + 1];
    float vx = (br & 2) ? 1.0f : -1.0f;
    float vy = (br & 1) ? 1.0f : -1.0f;
    float cyp = __fadd_rn(cy, vx * 0.015625f);   // +- 1/64 (exact)
    float cxp = __fadd_rn(cx, vy * 0.015625f);
    float fy = rintf(gridpos(cyp, 64.0f));
    float fx = rintf(gridpos(cxp, 64.0f));
    bool valid = (fy >= 0.0f) && (fy < 64.0f) && (fx >= 0.0f) && (fx < 64.0f);
    int iy = (int)fminf(fmaxf(fy, 0.0f), 63.0f);
    int ix = (int)fminf(fmaxf(fx, 0.0f), 63.0f);
    float qc0 = valid ? (-1.0f + (float)(2 * iy + 1) * 0.015625f) : 0.0f;
    float qc1 = valid ? (-1.0f + (float)(2 * ix + 1) * 0.015625f) : 0.0f;
    g_rel[2 * (size_t)r]     = __fmul_rn(__fsub_rn(cy, qc0), 64.0f);
    g_rel[2 * (size_t)r + 1] = __fmul_rn(__fsub_rn(cx, qc1), 64.0f);
    g_cellidx[r] = valid ? (b * 4096 + iy * 64 + ix) : -1;
}

// Gather q_guide_hr per point (128 channels) from HWC hr.
__global__ void k_gather_g(const float* __restrict__ coord) {
    int p = blockIdx.x;
    int c = threadIdx.x;    // 0..127
    int b = p >> 16;
    float cy = coord[2 * (size_t)p], cx = coord[2 * (size_t)p + 1];
    float fy = rintf(gridpos(cy, 256.0f));
    float fx = rintf(gridpos(cx, 256.0f));
    bool valid = (fy >= 0.0f) && (fy < 256.0f) && (fx >= 0.0f) && (fx < 256.0f);
    int iy = (int)fminf(fmaxf(fy, 0.0f), 255.0f);
    int ix = (int)fminf(fmaxf(fx, 0.0f), 255.0f);
    float v = 0.0f;
    if (valid) v = g_Thr[(((size_t)b * 256 + iy) * 256 + ix) * 128 + c];
    g_G[(size_t)p * 128 + c] = v;
}

// ------------------------- fp32 GEMM (128x128x8, 256 thr, 8x8) --------------
__global__ void __launch_bounds__(256)
k_sgemm(const float* __restrict__ A, const float* __restrict__ W,
        const float* __restrict__ bias, float* __restrict__ C,
        int M, int N, int K, int relu) {
    __shared__ float As[8][128];
    __shared__ float Bs[8][128];
    int tid = threadIdx.x;
    size_t m0 = (size_t)blockIdx.y * 128;
    int    n0 = blockIdx.x * 128;
    int ty = tid >> 4, tx = tid & 15;

    int aRow = tid >> 1;
    int aCol = (tid & 1) * 4;
    int bRow = tid >> 5;
    int bCol = (tid & 31) * 4;
    const float* Aptr = A + (m0 + aRow) * (size_t)K + aCol;
    const float* Wptr = W + (size_t)bRow * N + n0 + bCol;

    float acc[8][8];
    #pragma unroll
    for (int i = 0; i < 8; i++)
        #pragma unroll
        for (int j = 0; j < 8; j++) acc[i][j] = 0.0f;

    for (int k0 = 0; k0 < K; k0 += 8) {
        float4 av = *(const float4*)(Aptr + k0);
        As[aCol + 0][aRow] = av.x;
        As[aCol + 1][aRow] = av.y;
        As[aCol + 2][aRow] = av.z;
        As[aCol + 3][aRow] = av.w;
        float4 wv = *(const float4*)(Wptr + (size_t)k0 * N);
        *(float4*)&Bs[bRow][bCol] = wv;
        __syncthreads();
        #pragma unroll
        for (int kk = 0; kk < 8; kk++) {
            float4 a0 = *(const float4*)&As[kk][ty * 8];
            float4 a1 = *(const float4*)&As[kk][ty * 8 + 4];
            float4 b0 = *(const float4*)&Bs[kk][tx * 8];
            float4 b1 = *(const float4*)&Bs[kk][tx * 8 + 4];
            float ra[8] = {a0.x, a0.y, a0.z, a0.w, a1.x, a1.y, a1.z, a1.w};
            float rb[8] = {b0.x, b0.y, b0.z, b0.w, b1.x, b1.y, b1.z, b1.w};
            #pragma unroll
            for (int i = 0; i < 8; i++)
                #pragma unroll
                for (int j = 0; j < 8; j++)
                    acc[i][j] += ra[i] * rb[j];
        }
        __syncthreads();
    }

    float bj[8];
    #pragma unroll
    for (int j = 0; j < 8; j++) bj[j] = bias ? bias[n0 + tx * 8 + j] : 0.0f;

    #pragma unroll
    for (int i = 0; i < 8; i++) {
        float v[8];
        #pragma unroll
        for (int j = 0; j < 8; j++) {
            v[j] = acc[i][j] + bj[j];
            if (relu) v[j] = fmaxf(v[j], 0.0f);
        }
        float* cptr = C + (m0 + ty * 8 + i) * (size_t)N + n0 + tx * 8;
        *(float4*)(cptr + 0) = make_float4(v[0], v[1], v[2], v[3]);
        *(float4*)(cptr + 4) = make_float4(v[4], v[5], v[6], v[7]);
    }
}

// H1[row] = relu(V[pt] + U[cell] + rel0*W0[384] + rel1*W0[385] + b0)
__global__ void __launch_bounds__(256)
k_assemble(const float* __restrict__ W0, const float* __restrict__ b0, int r0) {
    int lr = blockIdx.x;            // 0..CHUNK_ROWS-1
    int r  = r0 + lr;
    int t  = threadIdx.x;           // 0..255 (float4 lanes of 1024)
    int p  = r >> 2;
    float rel0 = g_rel[2 * (size_t)r];
    float rel1 = g_rel[2 * (size_t)r + 1];
    int ci = g_cellidx[r];
    float4 v = ((const float4*)(g_V + (size_t)p * 1024))[t];
    float4 u = make_float4(0.f, 0.f, 0.f, 0.f);
    if (ci >= 0) u = ((const float4*)(g_U + (size_t)ci * 1024))[t];
    float4 wa = ((const float4*)(W0 + (size_t)384 * 1024))[t];
    float4 wb = ((const float4*)(W0 + (size_t)385 * 1024))[t];
    float4 bb = ((const float4*)b0)[t];
    float4 h;
    h.x = fmaxf(v.x + u.x + rel0 * wa.x + rel1 * wb.x + bb.x, 0.0f);
    h.y = fmaxf(v.y + u.y + rel0 * wa.y + rel1 * wb.y + bb.y, 0.0f);
    h.z = fmaxf(v.z + u.z + rel0 * wa.z + rel1 * wb.z + bb.z, 0.0f);
    h.w = fmaxf(v.w + u.w + rel0 * wa.w + rel1 * wb.w + bb.w, 0.0f);
    ((float4*)(g_H1 + (size_t)lr * 1024))[t] = h;
}

// Final layer (128->2) + softmax blend of the 4 branches.
__global__ void __launch_bounds__(256)
k_combine(const float* __restrict__ W4, const float* __restrict__ b4,
          float* __restrict__ out, int p0) {
    __shared__ float sw0[128], sw1[128];
    __shared__ float sy0[256], sy1[256];
    int t = threadIdx.x;
    if (t < 128) { sw0[t] = W4[2 * t]; sw1[t] = W4[2 * t + 1]; }
    __syncthreads();
    size_t lrow = (size_t)blockIdx.x * 256 + t;   // row within chunk
    const float4* h = (const float4*)(g_H4 + lrow * 128);
    float a0 = 0.0f, a1 = 0.0f;
    #pragma unroll
    for (int i = 0; i < 32; i++) {
        float4 v = h[i];
        int j = 4 * i;
        a0 += v.x * sw0[j] + v.y * sw0[j + 1] + v.z * sw0[j + 2] + v.w * sw0[j + 3];
        a1 += v.x * sw1[j] + v.y * sw1[j + 1] + v.z * sw1[j + 2] + v.w * sw1[j + 3];
    }
    sy0[t] = a0 + b4[0];
    sy1[t] = a1 + b4[1];
    __syncthreads();
    if (t < 64) {
        int base = t * 4;
        float m = fmaxf(fmaxf(sy1[base], sy1[base + 1]),
                        fmaxf(sy1[base + 2], sy1[base + 3]));
        float e0 = expf(sy1[base + 0] - m);
        float e1 = expf(sy1[base + 1] - m);
        float e2 = expf(sy1[base + 2] - m);
        float e3 = expf(sy1[base + 3] - m);
        float s   = e0 + e1 + e2 + e3;
        float num = sy0[base + 0] * e0 + sy0[base + 1] * e1 +
                    sy0[base + 2] * e2 + sy0[base + 3] * e3;
        out[(size_t)p0 + (size_t)blockIdx.x * 64 + t] = num / s;
    }
}

// ------------------------- launch -------------------------------------------
extern "C" void kernel_launch(void* const* d_in, const int* in_sizes, int n_in,
                              void* d_out, int out_size) {
    const float* feat  = (const float*)d_in[0];
    const float* coord = (const float*)d_in[1];
    const float* hr    = (const float*)d_in[2];
    const float* lr    = (const float*)d_in[3];
    const float* W0 = (const float*)d_in[4];
    const float* b0 = (const float*)d_in[5];
    const float* W1 = (const float*)d_in[6];
    const float* b1 = (const float*)d_in[7];
    const float* W2 = (const float*)d_in[8];
    const float* b2 = (const float*)d_in[9];
    const float* W3 = (const float*)d_in[10];
    const float* b3 = (const float*)d_in[11];
    const float* W4 = (const float*)d_in[12];
    const float* b4 = (const float*)d_in[13];
    float* out = (float*)d_out;

    float *pG, *pV, *pCellIn, *pU, *pWcell, *pWhr, *pH1, *pH2, *pH3, *pH4;
    cudaGetSymbolAddress((void**)&pG,      g_G);
    cudaGetSymbolAddress((void**)&pV,      g_V);
    cudaGetSymbolAddress((void**)&pCellIn, g_CellIn);
    cudaGetSymbolAddress((void**)&pU,      g_U);
    cudaGetSymbolAddress((void**)&pWcell,  g_Wcell);
    cudaGetSymbolAddress((void**)&pWhr,    g_Whr);
    cudaGetSymbolAddress((void**)&pH1,     g_H1);
    cudaGetSymbolAddress((void**)&pH2,     g_H2);
    cudaGetSymbolAddress((void**)&pH3,     g_H3);
    cudaGetSymbolAddress((void**)&pH4,     g_H4);

    // Front end
    k_transpose_hr<<<dim3(2048, 4, BATCH), dim3(32, 8)>>>(hr);
    k_build_w<<<1536, 256>>>(W0);
    k_build_cellin<<<16384, 256>>>(feat, lr);
    k_index<<<RTOT / 256, 256>>>(coord);
    k_gather_g<<<PTOT, 128>>>(coord);

    // U = CellIn @ Wcell   [16384 x 256] @ [256 x 1024]
    k_sgemm<<<dim3(1024 / 128, 16384 / 128), 256>>>(
        pCellIn, pWcell, nullptr, pU, 16384, 1024, 256, 0);
    // V = G @ Whr          [262144 x 128] @ [128 x 1024]
    k_sgemm<<<dim3(1024 / 128, PTOT / 128), 256>>>(
        pG, pWhr, nullptr, pV, PTOT, 1024, 128, 0);

    // Backend in 4 chunks of 262144 rows
    for (int c = 0; c < NCHUNK; c++) {
        int r0 = c * CHUNK_ROWS;
        int p0 = c * CHUNK_PTS;
        k_assemble<<<CHUNK_ROWS, 256>>>(W0, b0, r0);
        k_sgemm<<<dim3(512 / 128, CHUNK_ROWS / 128), 256>>>(
            pH1, W1, b1, pH2, CHUNK_ROWS, 512, 1024, 1);
        k_sgemm<<<dim3(256 / 128, CHUNK_ROWS / 128), 256>>>(
            pH2, W2, b2, pH3, CHUNK_ROWS, 256, 512, 1);
        k_sgemm<<<dim3(128 / 128, CHUNK_ROWS / 128), 256>>>(
            pH3, W3, b3, pH4, CHUNK_ROWS, 128, 256, 1);
        k_combine<<<CHUNK_PTS / 64, 256>>>(W4, b4, out, p0);
    }
    (void)in_sizes; (void)n_in; (void)out_size;
}

// round 2
// speedup vs baseline: 1.0003x; 1.0003x over previous
#include <cuda_runtime.h>
#include <math.h>

// ---------------------------------------------------------------------------
// JIIF pipeline, fp32 baseline with layer-0 factorization.
//
// Shapes (fixed by the problem):
//   feat      [4,128,64,64]
//   coord     [4,65536,2]
//   hr_guide  [4,128,256,256]
//   lr_guide  [4,128,64,64]
//   W0 [386,1024] b0[1024]; W1[1024,512]; W2[512,256]; W3[256,128]; W4[128,2]
//   out       [4,65536,1]  (float32, 262144 elems)
// ---------------------------------------------------------------------------

namespace {
constexpr int BATCH   = 4;
constexpr int NPTS    = 65536;            // points per batch
constexpr int PTOT    = BATCH * NPTS;     // 262144
constexpr int RTOT    = PTOT * 4;         // 1048576 rows
constexpr int CHUNK_PTS  = 65536;         // points per backend chunk
constexpr int CHUNK_ROWS = CHUNK_PTS * 4; // 262144
constexpr int NCHUNK  = 4;
}

// ------------------------------- scratch -----------------------------------
__device__ __align__(256) float g_Thr[(size_t)BATCH * 256 * 256 * 128]; // hr in HWC
__device__ __align__(256) float g_G[(size_t)PTOT * 128];                // gathered hr per point
__device__ __align__(256) float g_V[(size_t)PTOT * 1024];               // per-point proj
__device__ __align__(256) float g_CellIn[(size_t)BATCH * 4096 * 256];   // [feat,lr] per cell
__device__ __align__(256) float g_U[(size_t)BATCH * 4096 * 1024];       // per-cell proj
__device__ __align__(256) float g_Wcell[256 * 1024];                    // [W0a; -W0c]
__device__ __align__(256) float g_Whr[128 * 1024];                      // W0b + W0c
__device__ __align__(256) int   g_cellidx[RTOT];
__device__ __align__(256) float g_rel[(size_t)RTOT * 2];
__device__ __align__(256) float g_H1[(size_t)CHUNK_ROWS * 1024];
__device__ __align__(256) float g_H2[(size_t)CHUNK_ROWS * 512];
__device__ __align__(256) float g_H3[(size_t)CHUNK_ROWS * 256];
__device__ __align__(256) float g_H4[(size_t)CHUNK_ROWS * 128];

// ------------------------- helpers ------------------------------------------
// ((c + 1) * n - 1) * 0.5, forced to plain rn ops (no FMA contraction) so the
// rounding matches the reference's separate mul/sub exactly.
__device__ __forceinline__ float gridpos(float c, float n) {
    return __fmul_rn(__fsub_rn(__fmul_rn(__fadd_rn(c, 1.0f), n), 1.0f), 0.5f);
}

// ------------------------- kernels ------------------------------------------

// hr_guide [B,C,H*W] -> g_Thr [B, H*W, C]   (C=128, S=65536)
__global__ void k_transpose_hr(const float* __restrict__ in) {
    __shared__ float t[32][33];
    const size_t S = 65536, C = 128;
    int b  = blockIdx.z;
    int s0 = blockIdx.x * 32;
    int c0 = blockIdx.y * 32;
    int x  = threadIdx.x;              // 0..31
    #pragma unroll
    for (int j = threadIdx.y; j < 32; j += 8)
        t[j][x] = in[((size_t)b * C + (c0 + j)) * S + s0 + x];
    __syncthreads();
    #pragma unroll
    for (int j = threadIdx.y; j < 32; j += 8)
        g_Thr[((size_t)b * S + (s0 + j)) * C + c0 + x] = t[x][j];
}

// Build Wcell = [W0 rows 0..127 ; -(W0 rows 256..383)] and Whr = W0[128:256]+W0[256:384]
__global__ void k_build_w(const float* __restrict__ W0) {
    int idx = blockIdx.x * 256 + threadIdx.x;
    if (idx < 256 * 1024) {
        int k = idx >> 10, j = idx & 1023;
        g_Wcell[idx] = (k < 128) ? W0[k * 1024 + j] : -W0[(128 + k) * 1024 + j];
    } else {
        int t = idx - 256 * 1024;   // < 128*1024
        int k = t >> 10, j = t & 1023;
        g_Whr[t] = W0[(128 + k) * 1024 + j] + W0[(256 + k) * 1024 + j];
    }
}

// CellIn[b, cell, 0:128]=feat[b,:,cell], [128:256]=lr[b,:,cell]
__global__ void k_build_cellin(const float* __restrict__ feat,
                               const float* __restrict__ lr) {
    int idx  = blockIdx.x * 256 + threadIdx.x;      // < 4*4096*256
    int c    = idx & 255;
    int cell = (idx >> 8) & 4095;
    int b    = idx >> 20;
    float v;
    if (c < 128) v = feat[((size_t)(b * 128 + c)) * 4096 + cell];
    else         v = lr  [((size_t)(b * 128 + (c - 128))) * 4096 + cell];
    g_CellIn[idx] = v;
}

// Per (point, branch): cell index (or -1) and rel_coord.
__global__ void k_index(const float* __restrict__ coord) {
    int r = blockIdx.x * 256 + threadIdx.x;   // < RTOT
    int br = r & 3;
    int p  = r >> 2;
    int b  = p >> 16;
    float cy = coord[2 * (size_t)p], cx = coord[2 * (size_t)p + 1];
    float vx = (br & 2) ? 1.0f : -1.0f;
    float vy = (br & 1) ? 1.0f : -1.0f;
    float cyp = __fadd_rn(cy, vx * 0.015625f);   // +- 1/64 (exact)
    float cxp = __fadd_rn(cx, vy * 0.015625f);
    float fy = rintf(gridpos(cyp, 64.0f));
    float fx = rintf(gridpos(cxp, 64.0f));
    bool valid = (fy >= 0.0f) && (fy < 64.0f) && (fx >= 0.0f) && (fx < 64.0f);
    int iy = (int)fminf(fmaxf(fy, 0.0f), 63.0f);
    int ix = (int)fminf(fmaxf(fx, 0.0f), 63.0f);
    float qc0 = valid ? (-1.0f + (float)(2 * iy + 1) * 0.015625f) : 0.0f;
    float qc1 = valid ? (-1.0f + (float)(2 * ix + 1) * 0.015625f) : 0.0f;
    g_rel[2 * (size_t)r]     = __fmul_rn(__fsub_rn(cy, qc0), 64.0f);
    g_rel[2 * (size_t)r + 1] = __fmul_rn(__fsub_rn(cx, qc1), 64.0f);
    g_cellidx[r] = valid ? (b * 4096 + iy * 64 + ix) : -1;
}

// Gather q_guide_hr per point (128 channels) from HWC hr.
__global__ void k_gather_g(const float* __restrict__ coord) {
    int p = blockIdx.x;
    int c = threadIdx.x;    // 0..127
    int b = p >> 16;
    float cy = coord[2 * (size_t)p], cx = coord[2 * (size_t)p + 1];
    float fy = rintf(gridpos(cy, 256.0f));
    float fx = rintf(gridpos(cx, 256.0f));
    bool valid = (fy >= 0.0f) && (fy < 256.0f) && (fx >= 0.0f) && (fx < 256.0f);
    int iy = (int)fminf(fmaxf(fy, 0.0f), 255.0f);
    int ix = (int)fminf(fmaxf(fx, 0.0f), 255.0f);
    float v = 0.0f;
    if (valid) v = g_Thr[(((size_t)b * 256 + iy) * 256 + ix) * 128 + c];
    g_G[(size_t)p * 128 + c] = v;
}

// ------------------------- fp32 GEMM (128x128x8, 256 thr, 8x8) --------------
__global__ void __launch_bounds__(256)
k_sgemm(const float* __restrict__ A, const float* __restrict__ W,
        const float* __restrict__ bias, float* __restrict__ C,
        int M, int N, int K, int relu) {
    __shared__ float As[8][128];
    __shared__ float Bs[8][128];
    int tid = threadIdx.x;
    size_t m0 = (size_t)blockIdx.y * 128;
    int    n0 = blockIdx.x * 128;
    int ty = tid >> 4, tx = tid & 15;

    int aRow = tid >> 1;
    int aCol = (tid & 1) * 4;
    int bRow = tid >> 5;
    int bCol = (tid & 31) * 4;
    const float* Aptr = A + (m0 + aRow) * (size_t)K + aCol;
    const float* Wptr = W + (size_t)bRow * N + n0 + bCol;

    float acc[8][8];
    #pragma unroll
    for (int i = 0; i < 8; i++)
        #pragma unroll
        for (int j = 0; j < 8; j++) acc[i][j] = 0.0f;

    for (int k0 = 0; k0 < K; k0 += 8) {
        float4 av = *(const float4*)(Aptr + k0);
        As[aCol + 0][aRow] = av.x;
        As[aCol + 1][aRow] = av.y;
        As[aCol + 2][aRow] = av.z;
        As[aCol + 3][aRow] = av.w;
        float4 wv = *(const float4*)(Wptr + (size_t)k0 * N);
        *(float4*)&Bs[bRow][bCol] = wv;
        __syncthreads();
        #pragma unroll
        for (int kk = 0; kk < 8; kk++) {
            float4 a0 = *(const float4*)&As[kk][ty * 8];
            float4 a1 = *(const float4*)&As[kk][ty * 8 + 4];
            float4 b0 = *(const float4*)&Bs[kk][tx * 8];
            float4 b1 = *(const float4*)&Bs[kk][tx * 8 + 4];
            float ra[8] = {a0.x, a0.y, a0.z, a0.w, a1.x, a1.y, a1.z, a1.w};
            float rb[8] = {b0.x, b0.y, b0.z, b0.w, b1.x, b1.y, b1.z, b1.w};
            #pragma unroll
            for (int i = 0; i < 8; i++)
                #pragma unroll
                for (int j = 0; j < 8; j++)
                    acc[i][j] += ra[i] * rb[j];
        }
        __syncthreads();
    }

    float bj[8];
    #pragma unroll
    for (int j = 0; j < 8; j++) bj[j] = bias ? bias[n0 + tx * 8 + j] : 0.0f;

    #pragma unroll
    for (int i = 0; i < 8; i++) {
        float v[8];
        #pragma unroll
        for (int j = 0; j < 8; j++) {
            v[j] = acc[i][j] + bj[j];
            if (relu) v[j] = fmaxf(v[j], 0.0f);
        }
        float* cptr = C + (m0 + ty * 8 + i) * (size_t)N + n0 + tx * 8;
        *(float4*)(cptr + 0) = make_float4(v[0], v[1], v[2], v[3]);
        *(float4*)(cptr + 4) = make_float4(v[4], v[5], v[6], v[7]);
    }
}

// H1[row] = relu(V[pt] + U[cell] + rel0*W0[384] + rel1*W0[385] + b0)
__global__ void __launch_bounds__(256)
k_assemble(const float* __restrict__ W0, const float* __restrict__ b0, int r0) {
    int lr = blockIdx.x;            // 0..CHUNK_ROWS-1
    int r  = r0 + lr;
    int t  = threadIdx.x;           // 0..255 (float4 lanes of 1024)
    int p  = r >> 2;
    float rel0 = g_rel[2 * (size_t)r];
    float rel1 = g_rel[2 * (size_t)r + 1];
    int ci = g_cellidx[r];
    float4 v = ((const float4*)(g_V + (size_t)p * 1024))[t];
    float4 u = make_float4(0.f, 0.f, 0.f, 0.f);
    if (ci >= 0) u = ((const float4*)(g_U + (size_t)ci * 1024))[t];
    float4 wa = ((const float4*)(W0 + (size_t)384 * 1024))[t];
    float4 wb = ((const float4*)(W0 + (size_t)385 * 1024))[t];
    float4 bb = ((const float4*)b0)[t];
    float4 h;
    h.x = fmaxf(v.x + u.x + rel0 * wa.x + rel1 * wb.x + bb.x, 0.0f);
    h.y = fmaxf(v.y + u.y + rel0 * wa.y + rel1 * wb.y + bb.y, 0.0f);
    h.z = fmaxf(v.z + u.z + rel0 * wa.z + rel1 * wb.z + bb.z, 0.0f);
    h.w = fmaxf(v.w + u.w + rel0 * wa.w + rel1 * wb.w + bb.w, 0.0f);
    ((float4*)(g_H1 + (size_t)lr * 1024))[t] = h;
}

// Final layer (128->2) + softmax blend of the 4 branches.
__global__ void __launch_bounds__(256)
k_combine(const float* __restrict__ W4, const float* __restrict__ b4,
          float* __restrict__ out, int p0) {
    __shared__ float sw0[128], sw1[128];
    __shared__ float sy0[256], sy1[256];
    int t = threadIdx.x;
    if (t < 128) { sw0[t] = W4[2 * t]; sw1[t] = W4[2 * t + 1]; }
    __syncthreads();
    size_t lrow = (size_t)blockIdx.x * 256 + t;   // row within chunk
    const float4* h = (const float4*)(g_H4 + lrow * 128);
    float a0 = 0.0f, a1 = 0.0f;
    #pragma unroll
    for (int i = 0; i < 32; i++) {
        float4 v = h[i];
        int j = 4 * i;
        a0 += v.x * sw0[j] + v.y * sw0[j + 1] + v.z * sw0[j + 2] + v.w * sw0[j + 3];
        a1 += v.x * sw1[j] + v.y * sw1[j + 1] + v.z * sw1[j + 2] + v.w * sw1[j + 3];
    }
    sy0[t] = a0 + b4[0];
    sy1[t] = a1 + b4[1];
    __syncthreads();
    if (t < 64) {
        int base = t * 4;
        float m = fmaxf(fmaxf(sy1[base], sy1[base + 1]),
                        fmaxf(sy1[base + 2], sy1[base + 3]));
        float e0 = expf(sy1[base + 0] - m);
        float e1 = expf(sy1[base + 1] - m);
        float e2 = expf(sy1[base + 2] - m);
        float e3 = expf(sy1[base + 3] - m);
        float s   = e0 + e1 + e2 + e3;
        float num = sy0[base + 0] * e0 + sy0[base + 1] * e1 +
                    sy0[base + 2] * e2 + sy0[base + 3] * e3;
        out[(size_t)p0 + (size_t)blockIdx.x * 64 + t] = num / s;
    }
}

// ------------------------- launch -------------------------------------------
extern "C" void kernel_launch(void* const* d_in, const int* in_sizes, int n_in,
                              void* d_out, int out_size) {
    const float* feat  = (const float*)d_in[0];
    const float* coord = (const float*)d_in[1];
    const float* hr    = (const float*)d_in[2];
    const float* lr    = (const float*)d_in[3];
    const float* W0 = (const float*)d_in[4];
    const float* b0 = (const float*)d_in[5];
    const float* W1 = (const float*)d_in[6];
    const float* b1 = (const float*)d_in[7];
    const float* W2 = (const float*)d_in[8];
    const float* b2 = (const float*)d_in[9];
    const float* W3 = (const float*)d_in[10];
    const float* b3 = (const float*)d_in[11];
    const float* W4 = (const float*)d_in[12];
    const float* b4 = (const float*)d_in[13];
    float* out = (float*)d_out;

    float *pG, *pV, *pCellIn, *pU, *pWcell, *pWhr, *pH1, *pH2, *pH3, *pH4;
    cudaGetSymbolAddress((void**)&pG,      g_G);
    cudaGetSymbolAddress((void**)&pV,      g_V);
    cudaGetSymbolAddress((void**)&pCellIn, g_CellIn);
    cudaGetSymbolAddress((void**)&pU,      g_U);
    cudaGetSymbolAddress((void**)&pWcell,  g_Wcell);
    cudaGetSymbolAddress((void**)&pWhr,    g_Whr);
    cudaGetSymbolAddress((void**)&pH1,     g_H1);
    cudaGetSymbolAddress((void**)&pH2,     g_H2);
    cudaGetSymbolAddress((void**)&pH3,     g_H3);
    cudaGetSymbolAddress((void**)&pH4,     g_H4);

    // Front end
    k_transpose_hr<<<dim3(2048, 4, BATCH), dim3(32, 8)>>>(hr);
    k_build_w<<<1536, 256>>>(W0);
    k_build_cellin<<<16384, 256>>>(feat, lr);
    k_index<<<RTOT / 256, 256>>>(coord);
    k_gather_g<<<PTOT, 128>>>(coord);

    // U = CellIn @ Wcell   [16384 x 256] @ [256 x 1024]
    k_sgemm<<<dim3(1024 / 128, 16384 / 128), 256>>>(
        pCellIn, pWcell, nullptr, pU, 16384, 1024, 256, 0);
    // V = G @ Whr          [262144 x 128] @ [128 x 1024]
    k_sgemm<<<dim3(1024 / 128, PTOT / 128), 256>>>(
        pG, pWhr, nullptr, pV, PTOT, 1024, 128, 0);

    // Backend in 4 chunks of 262144 rows
    for (int c = 0; c < NCHUNK; c++) {
        int r0 = c * CHUNK_ROWS;
        int p0 = c * CHUNK_PTS;
        k_assemble<<<CHUNK_ROWS, 256>>>(W0, b0, r0);
        k_sgemm<<<dim3(512 / 128, CHUNK_ROWS / 128), 256>>>(
            pH1, W1, b1, pH2, CHUNK_ROWS, 512, 1024, 1);
        k_sgemm<<<dim3(256 / 128, CHUNK_ROWS / 128), 256>>>(
            pH2, W2, b2, pH3, CHUNK_ROWS, 256, 512, 1);
        k_sgemm<<<dim3(128 / 128, CHUNK_ROWS / 128), 256>>>(
            pH3, W3, b3, pH4, CHUNK_ROWS, 128, 256, 1);
        k_combine<<<CHUNK_PTS / 64, 256>>>(W4, b4, out, p0);
    }
    (void)in_sizes; (void)n_in; (void)out_size;
}

// round 5
// speedup vs baseline: 2.2554x; 2.2548x over previous
#include <cuda_runtime.h>
#include <cuda_bf16.h>
#include <math.h>
#include <stdint.h>

namespace {
constexpr int BATCH = 4;
constexpr int NPTS  = 65536;
constexpr int PTOT  = BATCH * NPTS;   // 262144
constexpr int RTOT  = PTOT * 4;       // 1048576
constexpr int CH    = 131072;         // rows per backend chunk
constexpr int NCHUNK = RTOT / CH;     // 8
constexpr uint32_t GSMEM = 131072;    // 2 stages x 64KB
}

// ------------------------------- scratch (total ~2.4 GB) --------------------
__device__ __align__(256) float g_Thr[(size_t)BATCH * 65536 * 128];
__device__ __align__(256) __nv_bfloat16 g_Ghi[(size_t)PTOT * 128];
__device__ __align__(256) __nv_bfloat16 g_Glo[(size_t)PTOT * 128];
__device__ __align__(256) float g_V[(size_t)PTOT * 1024];
__device__ __align__(256) float g_CellIn[(size_t)BATCH * 4096 * 256];
__device__ __align__(256) float g_U[(size_t)BATCH * 4096 * 1024];
__device__ __align__(256) float g_Wcell[256 * 1024];
__device__ __align__(256) __nv_bfloat16 g_WhrThi[1024 * 128], g_WhrTlo[1024 * 128];
__device__ __align__(256) __nv_bfloat16 g_W1thi[512 * 1024],  g_W1tlo[512 * 1024];
__device__ __align__(256) __nv_bfloat16 g_W2thi[256 * 512],   g_W2tlo[256 * 512];
__device__ __align__(256) __nv_bfloat16 g_W3thi[128 * 256],   g_W3tlo[128 * 256];
__device__ __align__(256) int   g_cellidx[RTOT];
__device__ __align__(256) float g_rel[(size_t)RTOT * 2];
__device__ __align__(256) __nv_bfloat16 g_H1hi[(size_t)CH * 1024], g_H1lo[(size_t)CH * 1024];
__device__ __align__(256) __nv_bfloat16 g_H2hi[(size_t)CH * 512],  g_H2lo[(size_t)CH * 512];
__device__ __align__(256) __nv_bfloat16 g_H3hi[(size_t)CH * 256],  g_H3lo[(size_t)CH * 256];
__device__ __align__(256) float g_H4[(size_t)CH * 128];

// ------------------------- PTX helpers --------------------------------------
__device__ __forceinline__ uint32_t smem_u32(const void* p) {
    uint32_t a;
    asm("{ .reg .u64 t; cvta.to.shared.u64 t, %1; cvt.u32.u64 %0, t; }" : "=r"(a) : "l"(p));
    return a;
}
__device__ __forceinline__ void cp16(uint32_t s, const void* g) {
    asm volatile("cp.async.cg.shared.global [%0], [%1], 16;" :: "r"(s), "l"(g));
}
__device__ __forceinline__ void cp_commit() {
    asm volatile("cp.async.commit_group;" ::: "memory");
}
template <int N>
__device__ __forceinline__ void cp_wait() {
    asm volatile("cp.async.wait_group %0;" :: "n"(N) : "memory");
}
__device__ __forceinline__ void ldm4(uint32_t* r, uint32_t a) {
    asm volatile("ldmatrix.sync.aligned.m8n8.x4.shared.b16 {%0,%1,%2,%3}, [%4];"
                 : "=r"(r[0]), "=r"(r[1]), "=r"(r[2]), "=r"(r[3]) : "r"(a));
}
__device__ __forceinline__ void mma16816(float* c, const uint32_t* a,
                                         uint32_t b0, uint32_t b1) {
    asm volatile("mma.sync.aligned.m16n8k16.row.col.f32.bf16.bf16.f32 "
                 "{%0,%1,%2,%3}, {%4,%5,%6,%7}, {%8,%9}, {%0,%1,%2,%3};"
                 : "+f"(c[0]), "+f"(c[1]), "+f"(c[2]), "+f"(c[3])
                 : "r"(a[0]), "r"(a[1]), "r"(a[2]), "r"(a[3]), "r"(b0), "r"(b1));
}

// ------------------------- front-end helpers ---------------------------------
__device__ __forceinline__ float gridpos(float c, float n) {
    return __fmul_rn(__fsub_rn(__fmul_rn(__fadd_rn(c, 1.0f), n), 1.0f), 0.5f);
}

__global__ void k_transpose_hr(const float* __restrict__ in) {
    __shared__ float t[32][33];
    const size_t S = 65536, C = 128;
    int b = blockIdx.z, s0 = blockIdx.x * 32, c0 = blockIdx.y * 32;
    int x = threadIdx.x;
    #pragma unroll
    for (int j = threadIdx.y; j < 32; j += 8)
        t[j][x] = in[((size_t)b * C + (c0 + j)) * S + s0 + x];
    __syncthreads();
    #pragma unroll
    for (int j = threadIdx.y; j < 32; j += 8)
        g_Thr[((size_t)b * S + (s0 + j)) * C + c0 + x] = t[x][j];
}

__global__ void k_build_wcell(const float* __restrict__ W0) {
    int idx = blockIdx.x * 256 + threadIdx.x;   // < 256*1024
    int k = idx >> 10, j = idx & 1023;
    g_Wcell[idx] = (k < 128) ? W0[k * 1024 + j] : -W0[(128 + k) * 1024 + j];
}

__global__ void k_build_whrt(const float* __restrict__ W0) {
    int idx = blockIdx.x * 256 + threadIdx.x;   // idx = n*128+k
    int n = idx >> 7, k = idx & 127;
    float w = W0[(size_t)(128 + k) * 1024 + n] + W0[(size_t)(256 + k) * 1024 + n];
    __nv_bfloat16 h = __float2bfloat16(w);
    g_WhrThi[idx] = h;
    g_WhrTlo[idx] = __float2bfloat16(w - __bfloat162float(h));
}

__global__ void k_wsplit(const float* __restrict__ W, __nv_bfloat16* __restrict__ Whi,
                         __nv_bfloat16* __restrict__ Wlo, int K, int N) {
    int idx = blockIdx.x * 256 + threadIdx.x;
    if (idx >= K * N) return;
    int k = idx / N, n = idx % N;
    float w = W[idx];
    __nv_bfloat16 h = __float2bfloat16(w);
    Whi[(size_t)n * K + k] = h;
    Wlo[(size_t)n * K + k] = __float2bfloat16(w - __bfloat162float(h));
}

__global__ void k_build_cellin(const float* __restrict__ feat,
                               const float* __restrict__ lr) {
    int idx = blockIdx.x * 256 + threadIdx.x;
    int c = idx & 255, cell = (idx >> 8) & 4095, b = idx >> 20;
    float v;
    if (c < 128) v = feat[((size_t)(b * 128 + c)) * 4096 + cell];
    else         v = lr[((size_t)(b * 128 + (c - 128))) * 4096 + cell];
    g_CellIn[idx] = v;
}

__global__ void k_index(const float* __restrict__ coord) {
    int r = blockIdx.x * 256 + threadIdx.x;
    int br = r & 3, p = r >> 2, b = p >> 16;
    float cy = coord[2 * (size_t)p], cx = coord[2 * (size_t)p + 1];
    float vx = (br & 2) ? 1.0f : -1.0f;
    float vy = (br & 1) ? 1.0f : -1.0f;
    float cyp = __fadd_rn(cy, vx * 0.015625f);
    float cxp = __fadd_rn(cx, vy * 0.015625f);
    float fy = rintf(gridpos(cyp, 64.0f));
    float fx = rintf(gridpos(cxp, 64.0f));
    bool valid = (fy >= 0.0f) && (fy < 64.0f) && (fx >= 0.0f) && (fx < 64.0f);
    int iy = (int)fminf(fmaxf(fy, 0.0f), 63.0f);
    int ix = (int)fminf(fmaxf(fx, 0.0f), 63.0f);
    float qc0 = valid ? (-1.0f + (float)(2 * iy + 1) * 0.015625f) : 0.0f;
    float qc1 = valid ? (-1.0f + (float)(2 * ix + 1) * 0.015625f) : 0.0f;
    g_rel[2 * (size_t)r]     = __fmul_rn(__fsub_rn(cy, qc0), 64.0f);
    g_rel[2 * (size_t)r + 1] = __fmul_rn(__fsub_rn(cx, qc1), 64.0f);
    g_cellidx[r] = valid ? (b * 4096 + iy * 64 + ix) : -1;
}

__global__ void k_gather_g(const float* __restrict__ coord) {
    int p = blockIdx.x;
    int c = threadIdx.x;   // 0..127
    int b = p >> 16;
    float cy = coord[2 * (size_t)p], cx = coord[2 * (size_t)p + 1];
    float fy = rintf(gridpos(cy, 256.0f));
    float fx = rintf(gridpos(cx, 256.0f));
    bool valid = (fy >= 0.0f) && (fy < 256.0f) && (fx >= 0.0f) && (fx < 256.0f);
    int iy = (int)fminf(fmaxf(fy, 0.0f), 255.0f);
    int ix = (int)fminf(fmaxf(fx, 0.0f), 255.0f);
    float v = 0.0f;
    if (valid) v = g_Thr[(((size_t)b * 256 + iy) * 256 + ix) * 128 + c];
    __nv_bfloat16 h = __float2bfloat16(v);
    g_Ghi[(size_t)p * 128 + c] = h;
    g_Glo[(size_t)p * 128 + c] = __float2bfloat16(v - __bfloat162float(h));
}

// ------------------------- fp32 SGEMM (U path only) --------------------------
__global__ void __launch_bounds__(256)
k_sgemm(const float* __restrict__ A, const float* __restrict__ W,
        float* __restrict__ C, int N, int K) {
    __shared__ float As[8][128];
    __shared__ float Bs[8][128];
    int tid = threadIdx.x;
    size_t m0 = (size_t)blockIdx.y * 128;
    int n0 = blockIdx.x * 128;
    int ty = tid >> 4, tx = tid & 15;
    int aRow = tid >> 1, aCol = (tid & 1) * 4;
    int bRow = tid >> 5, bCol = (tid & 31) * 4;
    const float* Aptr = A + (m0 + aRow) * (size_t)K + aCol;
    const float* Wptr = W + (size_t)bRow * N + n0 + bCol;
    float acc[8][8];
    #pragma unroll
    for (int i = 0; i < 8; i++)
        #pragma unroll
        for (int j = 0; j < 8; j++) acc[i][j] = 0.0f;
    for (int k0 = 0; k0 < K; k0 += 8) {
        float4 av = *(const float4*)(Aptr + k0);
        As[aCol + 0][aRow] = av.x; As[aCol + 1][aRow] = av.y;
        As[aCol + 2][aRow] = av.z; As[aCol + 3][aRow] = av.w;
        *(float4*)&Bs[bRow][bCol] = *(const float4*)(Wptr + (size_t)k0 * N);
        __syncthreads();
        #pragma unroll
        for (int kk = 0; kk < 8; kk++) {
            float4 a0 = *(const float4*)&As[kk][ty * 8];
            float4 a1 = *(const float4*)&As[kk][ty * 8 + 4];
            float4 b0 = *(const float4*)&Bs[kk][tx * 8];
            float4 b1 = *(const float4*)&Bs[kk][tx * 8 + 4];
            float ra[8] = {a0.x, a0.y, a0.z, a0.w, a1.x, a1.y, a1.z, a1.w};
            float rb[8] = {b0.x, b0.y, b0.z, b0.w, b1.x, b1.y, b1.z, b1.w};
            #pragma unroll
            for (int i = 0; i < 8; i++)
                #pragma unroll
                for (int j = 0; j < 8; j++) acc[i][j] += ra[i] * rb[j];
        }
        __syncthreads();
    }
    #pragma unroll
    for (int i = 0; i < 8; i++) {
        float* cptr = C + (m0 + ty * 8 + i) * (size_t)N + n0 + tx * 8;
        *(float4*)(cptr + 0) = make_float4(acc[i][0], acc[i][1], acc[i][2], acc[i][3]);
        *(float4*)(cptr + 4) = make_float4(acc[i][4], acc[i][5], acc[i][6], acc[i][7]);
    }
}

// ---------------- HMMA split-bf16 GEMM (BM=128, BN=128, BK=64) ---------------
// C = (Ahi+Alo) @ (Whi+Wlo)^T (3-term). Wt stored [N,K] K-contiguous.
// flags: 1=bias, 2=relu, 4=f32 out (else hi/lo bf16 out).
__global__ void __launch_bounds__(256, 1)
k_hgemm(const __nv_bfloat16* __restrict__ Ahi, const __nv_bfloat16* __restrict__ Alo,
        const __nv_bfloat16* __restrict__ Whi, const __nv_bfloat16* __restrict__ Wlo,
        const float* __restrict__ bias, float* __restrict__ Cf,
        __nv_bfloat16* __restrict__ Chi, __nv_bfloat16* __restrict__ Clo,
        int N, int K, int flags) {
    extern __shared__ char smem[];
    const uint32_t sb = smem_u32(smem);
    const int tid = threadIdx.x, wid = tid >> 5, lane = tid & 31;
    const int wm = wid & 3, wn = wid >> 2;         // 4 x 2 warp grid
    const size_t m0 = (size_t)blockIdx.y * 128;
    const int n0 = blockIdx.x * 128;

    float acc[2][8][4];
    #pragma unroll
    for (int i = 0; i < 2; i++)
        #pragma unroll
        for (int j = 0; j < 8; j++)
            #pragma unroll
            for (int q = 0; q < 4; q++) acc[i][j][q] = 0.0f;

    // stage layout: Ahi@0, Alo@16K, Whi@32K, Wlo@48K; stage stride 64K
    auto load_stage = [&](int s, int ch) {
        uint32_t base = sb + s * 65536;
        int k0 = ch << 6;
        #pragma unroll
        for (int i = 0; i < 4; i++) {
            int idx = tid + (i << 8);        // 0..1023
            int r = idx >> 3, c8 = idx & 7;
            uint32_t off = r * 128 + ((c8 ^ (r & 7)) << 4);
            size_t ga = (m0 + r) * (size_t)K + k0 + (c8 << 3);
            size_t gw = (size_t)(n0 + r) * K + k0 + (c8 << 3);
            cp16(base + off,         Ahi + ga);
            cp16(base + 16384 + off, Alo + ga);
            cp16(base + 32768 + off, Whi + gw);
            cp16(base + 49152 + off, Wlo + gw);
        }
        cp_commit();
    };

    const int NC = K >> 6;
    load_stage(0, 0);
    if (NC > 1) load_stage(1, 1);

    for (int ch = 0; ch < NC; ch++) {
        if (ch + 1 < NC) cp_wait<1>(); else cp_wait<0>();
        __syncthreads();
        uint32_t st = sb + (ch & 1) * 65536;
        uint32_t aB[3] = {st, st + 16384, st};
        uint32_t wB[3] = {st + 32768, st + 32768, st + 49152};
        #pragma unroll
        for (int p = 0; p < 3; p++) {
            #pragma unroll
            for (int ks = 0; ks < 4; ks++) {
                uint32_t af[2][4];
                #pragma unroll
                for (int mt = 0; mt < 2; mt++) {
                    int r = wm * 32 + mt * 16 + (lane & 15);
                    int c8 = 2 * ks + (lane >> 4);
                    ldm4(af[mt], aB[p] + r * 128 + ((c8 ^ (r & 7)) << 4));
                }
                uint32_t bfr[4][4];
                #pragma unroll
                for (int pi = 0; pi < 4; pi++) {
                    int r = wn * 64 + pi * 16 + (lane & 15);
                    int c8 = 2 * ks + (lane >> 4);
                    ldm4(bfr[pi], wB[p] + r * 128 + ((c8 ^ (r & 7)) << 4));
                }
                #pragma unroll
                for (int mt = 0; mt < 2; mt++)
                    #pragma unroll
                    for (int pi = 0; pi < 4; pi++) {
                        mma16816(acc[mt][2 * pi],     af[mt], bfr[pi][0], bfr[pi][2]);
                        mma16816(acc[mt][2 * pi + 1], af[mt], bfr[pi][1], bfr[pi][3]);
                    }
            }
        }
        __syncthreads();
        if (ch + 2 < NC) load_stage(ch & 1, ch + 2);
    }

    // ------------------------------- epilogue --------------------------------
    const int g8 = lane >> 2, tig = lane & 3;
    #pragma unroll
    for (int mt = 0; mt < 2; mt++) {
        size_t rbase = m0 + wm * 32 + mt * 16 + g8;
        #pragma unroll
        for (int nt = 0; nt < 8; nt++) {
            int col = n0 + wn * 64 + nt * 8 + tig * 2;
            float bb0 = 0.0f, bb1 = 0.0f;
            if (flags & 1) { bb0 = bias[col]; bb1 = bias[col + 1]; }
            #pragma unroll
            for (int h = 0; h < 2; h++) {
                size_t row = rbase + h * 8;
                float v0 = acc[mt][nt][2 * h]     + bb0;
                float v1 = acc[mt][nt][2 * h + 1] + bb1;
                if (flags & 2) { v0 = fmaxf(v0, 0.0f); v1 = fmaxf(v1, 0.0f); }
                if (flags & 4) {
                    float2 vv = make_float2(v0, v1);
                    *(float2*)(Cf + row * (size_t)N + col) = vv;
                } else {
                    __nv_bfloat16 h0 = __float2bfloat16(v0);
                    __nv_bfloat16 h1 = __float2bfloat16(v1);
                    __nv_bfloat16 l0 = __float2bfloat16(v0 - __bfloat162float(h0));
                    __nv_bfloat16 l1 = __float2bfloat16(v1 - __bfloat162float(h1));
                    __nv_bfloat162 hh; hh.x = h0; hh.y = h1;
                    __nv_bfloat162 ll; ll.x = l0; ll.y = l1;
                    *(__nv_bfloat162*)(Chi + row * (size_t)N + col) = hh;
                    *(__nv_bfloat162*)(Clo + row * (size_t)N + col) = ll;
                }
            }
        }
    }
}

// H1[lr] = relu(V[pt] + U[cell] + rel0*w384 + rel1*w385 + b0) -> hi/lo bf16
__global__ void __launch_bounds__(256)
k_assemble(const float* __restrict__ W0, const float* __restrict__ b0, int r0) {
    int lr = blockIdx.x;
    int r  = r0 + lr;
    int t  = threadIdx.x;
    int p  = r >> 2;
    float rel0 = g_rel[2 * (size_t)r];
    float rel1 = g_rel[2 * (size_t)r + 1];
    int ci = g_cellidx[r];
    float4 v = ((const float4*)(g_V + (size_t)p * 1024))[t];
    float4 u = make_float4(0.f, 0.f, 0.f, 0.f);
    if (ci >= 0) u = ((const float4*)(g_U + (size_t)ci * 1024))[t];
    float4 wa = ((const float4*)(W0 + (size_t)384 * 1024))[t];
    float4 wb = ((const float4*)(W0 + (size_t)385 * 1024))[t];
    float4 bb = ((const float4*)b0)[t];
    float h[4];
    h[0] = fmaxf(v.x + u.x + rel0 * wa.x + rel1 * wb.x + bb.x, 0.0f);
    h[1] = fmaxf(v.y + u.y + rel0 * wa.y + rel1 * wb.y + bb.y, 0.0f);
    h[2] = fmaxf(v.z + u.z + rel0 * wa.z + rel1 * wb.z + bb.z, 0.0f);
    h[3] = fmaxf(v.w + u.w + rel0 * wa.w + rel1 * wb.w + bb.w, 0.0f);
    __nv_bfloat16 hh[4], ll[4];
    #pragma unroll
    for (int i = 0; i < 4; i++) {
        hh[i] = __float2bfloat16(h[i]);
        ll[i] = __float2bfloat16(h[i] - __bfloat162float(hh[i]));
    }
    *(uint2*)(g_H1hi + (size_t)lr * 1024 + 4 * t) = *(uint2*)hh;
    *(uint2*)(g_H1lo + (size_t)lr * 1024 + 4 * t) = *(uint2*)ll;
}

// Final layer (128->2) + softmax blend of the 4 branches (per chunk).
__global__ void __launch_bounds__(256)
k_combine(const float* __restrict__ W4, const float* __restrict__ b4,
          float* __restrict__ out, int p0) {
    __shared__ float sw0[128], sw1[128];
    __shared__ float sy0[256], sy1[256];
    int t = threadIdx.x;
    if (t < 128) { sw0[t] = W4[2 * t]; sw1[t] = W4[2 * t + 1]; }
    __syncthreads();
    size_t lrow = (size_t)blockIdx.x * 256 + t;
    const float4* h = (const float4*)(g_H4 + lrow * 128);
    float a0 = 0.0f, a1 = 0.0f;
    #pragma unroll
    for (int i = 0; i < 32; i++) {
        float4 v = h[i];
        int j = 4 * i;
        a0 += v.x * sw0[j] + v.y * sw0[j + 1] + v.z * sw0[j + 2] + v.w * sw0[j + 3];
        a1 += v.x * sw1[j] + v.y * sw1[j + 1] + v.z * sw1[j + 2] + v.w * sw1[j + 3];
    }
    sy0[t] = a0 + b4[0];
    sy1[t] = a1 + b4[1];
    __syncthreads();
    if (t < 64) {
        int base = t * 4;
        float m = fmaxf(fmaxf(sy1[base], sy1[base + 1]),
                        fmaxf(sy1[base + 2], sy1[base + 3]));
        float e0 = expf(sy1[base + 0] - m);
        float e1 = expf(sy1[base + 1] - m);
        float e2 = expf(sy1[base + 2] - m);
        float e3 = expf(sy1[base + 3] - m);
        float s = e0 + e1 + e2 + e3;
        float num = sy0[base + 0] * e0 + sy0[base + 1] * e1 +
                    sy0[base + 2] * e2 + sy0[base + 3] * e3;
        out[(size_t)p0 + (size_t)blockIdx.x * 64 + t] = num / s;
    }
}

// ------------------------- launch -------------------------------------------
extern "C" void kernel_launch(void* const* d_in, const int* in_sizes, int n_in,
                              void* d_out, int out_size) {
    const float* feat  = (const float*)d_in[0];
    const float* coord = (const float*)d_in[1];
    const float* hr    = (const float*)d_in[2];
    const float* lr    = (const float*)d_in[3];
    const float* W0 = (const float*)d_in[4];
    const float* b0 = (const float*)d_in[5];
    const float* W1 = (const float*)d_in[6];
    const float* b1 = (const float*)d_in[7];
    const float* W2 = (const float*)d_in[8];
    const float* b2 = (const float*)d_in[9];
    const float* W3 = (const float*)d_in[10];
    const float* b3 = (const float*)d_in[11];
    const float* W4 = (const float*)d_in[12];
    const float* b4 = (const float*)d_in[13];
    float* out = (float*)d_out;

    cudaFuncSetAttribute(k_hgemm, cudaFuncAttributeMaxDynamicSharedMemorySize, GSMEM);

    void *pGhi, *pGlo, *pV, *pCellIn, *pU, *pWcell;
    void *pWhrThi, *pWhrTlo, *pW1hi, *pW1lo, *pW2hi, *pW2lo, *pW3hi, *pW3lo;
    void *pH1hi, *pH1lo, *pH2hi, *pH2lo, *pH3hi, *pH3lo, *pH4;
    cudaGetSymbolAddress(&pGhi, g_Ghi);       cudaGetSymbolAddress(&pGlo, g_Glo);
    cudaGetSymbolAddress(&pV, g_V);           cudaGetSymbolAddress(&pCellIn, g_CellIn);
    cudaGetSymbolAddress(&pU, g_U);           cudaGetSymbolAddress(&pWcell, g_Wcell);
    cudaGetSymbolAddress(&pWhrThi, g_WhrThi); cudaGetSymbolAddress(&pWhrTlo, g_WhrTlo);
    cudaGetSymbolAddress(&pW1hi, g_W1thi);    cudaGetSymbolAddress(&pW1lo, g_W1tlo);
    cudaGetSymbolAddress(&pW2hi, g_W2thi);    cudaGetSymbolAddress(&pW2lo, g_W2tlo);
    cudaGetSymbolAddress(&pW3hi, g_W3thi);    cudaGetSymbolAddress(&pW3lo, g_W3tlo);
    cudaGetSymbolAddress(&pH1hi, g_H1hi);     cudaGetSymbolAddress(&pH1lo, g_H1lo);
    cudaGetSymbolAddress(&pH2hi, g_H2hi);     cudaGetSymbolAddress(&pH2lo, g_H2lo);
    cudaGetSymbolAddress(&pH3hi, g_H3hi);     cudaGetSymbolAddress(&pH3lo, g_H3lo);
    cudaGetSymbolAddress(&pH4, g_H4);

    // Front end
    k_transpose_hr<<<dim3(2048, 4, BATCH), dim3(32, 8)>>>(hr);
    k_build_wcell<<<1024, 256>>>(W0);
    k_build_whrt<<<512, 256>>>(W0);
    k_wsplit<<<2048, 256>>>(W1, (__nv_bfloat16*)pW1hi, (__nv_bfloat16*)pW1lo, 1024, 512);
    k_wsplit<<<512, 256>>>(W2, (__nv_bfloat16*)pW2hi, (__nv_bfloat16*)pW2lo, 512, 256);
    k_wsplit<<<128, 256>>>(W3, (__nv_bfloat16*)pW3hi, (__nv_bfloat16*)pW3lo, 256, 128);
    k_build_cellin<<<16384, 256>>>(feat, lr);
    k_index<<<RTOT / 256, 256>>>(coord);
    k_gather_g<<<PTOT, 128>>>(coord);

    // U = CellIn @ Wcell (fp32, small)
    k_sgemm<<<dim3(8, 128), 256>>>((const float*)pCellIn, (const float*)pWcell,
                                   (float*)pU, 1024, 256);

    // V = G @ WhrT^T  [262144 x 1024], K=128
    k_hgemm<<<dim3(8, PTOT / 128), 256, GSMEM>>>(
        (const __nv_bfloat16*)pGhi, (const __nv_bfloat16*)pGlo,
        (const __nv_bfloat16*)pWhrThi, (const __nv_bfloat16*)pWhrTlo,
        nullptr, (float*)pV, nullptr, nullptr, 1024, 128, 4);

    // Backend in 8 chunks of CH rows
    for (int c = 0; c < NCHUNK; c++) {
        int r0 = c * CH;
        int p0 = c * (CH / 4);
        k_assemble<<<CH, 256>>>(W0, b0, r0);
        // L1: [CH x 512], K=1024
        k_hgemm<<<dim3(4, CH / 128), 256, GSMEM>>>(
            (const __nv_bfloat16*)pH1hi, (const __nv_bfloat16*)pH1lo,
            (const __nv_bfloat16*)pW1hi, (const __nv_bfloat16*)pW1lo,
            b1, nullptr, (__nv_bfloat16*)pH2hi, (__nv_bfloat16*)pH2lo, 512, 1024, 3);
        // L2: [CH x 256], K=512
        k_hgemm<<<dim3(2, CH / 128), 256, GSMEM>>>(
            (const __nv_bfloat16*)pH2hi, (const __nv_bfloat16*)pH2lo,
            (const __nv_bfloat16*)pW2hi, (const __nv_bfloat16*)pW2lo,
            b2, nullptr, (__nv_bfloat16*)pH3hi, (__nv_bfloat16*)pH3lo, 256, 512, 3);
        // L3: [CH x 128], K=256 -> fp32 H4
        k_hgemm<<<dim3(1, CH / 128), 256, GSMEM>>>(
            (const __nv_bfloat16*)pH3hi, (const __nv_bfloat16*)pH3lo,
            (const __nv_bfloat16*)pW3hi, (const __nv_bfloat16*)pW3lo,
            b3, (float*)pH4, nullptr, nullptr, 128, 256, 7);
        k_combine<<<CH / 4 / 64, 256>>>(W4, b4, out, p0);
    }
    (void)in_sizes; (void)n_in; (void)out_size;
}